// round 1
// baseline (speedup 1.0000x reference)
#include <cuda_runtime.h>

#define B_   32
#define C_   384
#define HW_  4096
#define M_   64
#define R_   16

#define CT     128   // c rows per block in pool kernel
#define NK     32    // K chunk
#define KSPLIT 4
#define KLEN   (HW_ / KSPLIT)   // 1024

// ---------------- f32x2 helpers (packed fp32 FMA, sm_100+) ----------------
__device__ __forceinline__ unsigned long long pk2(float lo, float hi) {
    unsigned long long r;
    asm("mov.b64 %0, {%1, %2};" : "=l"(r) : "f"(lo), "f"(hi));
    return r;
}
__device__ __forceinline__ float2 unpk2(unsigned long long v) {
    float2 u;
    asm("mov.b64 {%0, %1}, %2;" : "=f"(u.x), "=f"(u.y) : "l"(v));
    return u;
}
__device__ __forceinline__ void fma2(unsigned long long &d, unsigned long long a,
                                     unsigned long long b) {
    asm("fma.rn.f32x2 %0, %1, %2, %0;" : "+l"(d) : "l"(a), "l"(b));
}

// ---------------- kernel 0: zero the T region of d_out ----------------
__global__ void k_zero(float* __restrict__ p, int n) {
    int i = blockIdx.x * blockDim.x + threadIdx.x;
    if (i < n) p[i] = 0.0f;
}

// ---------------- kernel 1: V = Vw x + Vb ; L = U V ; S = softmax_M(L) ----
// grid (HW_/128, B_), 128 threads; each thread owns one pixel n.
__global__ __launch_bounds__(128) void k_proj_softmax(
    const float* __restrict__ x,  const float* __restrict__ Vw,
    const float* __restrict__ Vb, const float* __restrict__ U,
    float* __restrict__ S)
{
    __shared__ unsigned long long sVw2[C_ * 8];   // [c][r2] pairs over r, 24KB
    __shared__ unsigned long long sUT2[R_ * 32];  // [r][m2] pairs over m, 4KB
    __shared__ float sVb[R_];

    const int tid = threadIdx.x;
    for (int i = tid; i < C_ * 8; i += 128) {
        int c = i >> 3, r2 = i & 7;
        sVw2[i] = pk2(Vw[(2 * r2) * C_ + c], Vw[(2 * r2 + 1) * C_ + c]);
    }
    for (int i = tid; i < R_ * 32; i += 128) {
        int r = i >> 5, m2 = i & 31;
        sUT2[i] = pk2(U[(2 * m2) * R_ + r], U[(2 * m2 + 1) * R_ + r]);
    }
    if (tid < R_) sVb[tid] = Vb[tid];
    __syncthreads();

    const int b = blockIdx.y;
    const int n = (blockIdx.x << 7) + tid;
    const float* xp = x + ((size_t)b * C_) * HW_ + n;

    unsigned long long V2[8];
#pragma unroll
    for (int r2 = 0; r2 < 8; r2++) V2[r2] = pk2(sVb[2 * r2], sVb[2 * r2 + 1]);

#pragma unroll 4
    for (int c = 0; c < C_; c++) {
        float xv = xp[(size_t)c * HW_];
        unsigned long long x2 = pk2(xv, xv);
#pragma unroll
        for (int r2 = 0; r2 < 8; r2++) fma2(V2[r2], x2, sVw2[c * 8 + r2]);
    }

    float V[R_];
#pragma unroll
    for (int r2 = 0; r2 < 8; r2++) {
        float2 u = unpk2(V2[r2]);
        V[2 * r2] = u.x; V[2 * r2 + 1] = u.y;
    }

    unsigned long long L2[32];
#pragma unroll
    for (int m2 = 0; m2 < 32; m2++) L2[m2] = 0ULL;
#pragma unroll
    for (int r = 0; r < R_; r++) {
        unsigned long long v2 = pk2(V[r], V[r]);
#pragma unroll
        for (int m2 = 0; m2 < 32; m2++) fma2(L2[m2], v2, sUT2[r * 32 + m2]);
    }

    float L[M_];
#pragma unroll
    for (int m2 = 0; m2 < 32; m2++) {
        float2 u = unpk2(L2[m2]);
        L[2 * m2] = u.x; L[2 * m2 + 1] = u.y;
    }
    float mx = -1e30f;
#pragma unroll
    for (int m = 0; m < M_; m++) mx = fmaxf(mx, L[m]);
    float sum = 0.0f;
#pragma unroll
    for (int m = 0; m < M_; m++) { L[m] = __expf(L[m] - mx); sum += L[m]; }
    float inv = 1.0f / sum;

    float* sp = S + ((size_t)b * M_) * HW_ + n;
#pragma unroll
    for (int m = 0; m < M_; m++) sp[(size_t)m * HW_] = L[m] * inv;
}

// ---------------- kernel 2: T[b,c,m] += sum_n x[b,c,n] * S[b,m,n] ----------
// grid (KSPLIT, C_/CT, B_), 128 threads. Thread tile: 8 c-rows x 8 m-cols
// (4 f32x2 pairs). atomicAdd into pre-zeroed T.
__global__ __launch_bounds__(128) void k_pool(
    const float* __restrict__ x, const float* __restrict__ S,
    float* __restrict__ T)
{
    __shared__ float xs[CT * (NK + 1)];               // padded stride 33
    __shared__ unsigned long long ss2[32 * (NK + 1)]; // [m2][j], padded stride 33

    const int tid = threadIdx.x;
    const int tx = tid & 7;        // 8 lanes over m
    const int ty = tid >> 3;       // 16 lanes over c (8 rows each)
    const int ks = blockIdx.x;
    const int c0 = blockIdx.y * CT;
    const int b  = blockIdx.z;

    const size_t xbase = ((size_t)b * C_ + c0) * HW_ + (size_t)ks * KLEN;
    const size_t sbase = ((size_t)b * M_) * HW_ + (size_t)ks * KLEN;

    unsigned long long acc[8][4];
#pragma unroll
    for (int cc = 0; cc < 8; cc++)
#pragma unroll
        for (int mp = 0; mp < 4; mp++) acc[cc][mp] = 0ULL;

    for (int k0 = 0; k0 < KLEN; k0 += NK) {
        __syncthreads();
        // load x tile [CT x NK]
#pragma unroll
        for (int it = 0; it < (CT * NK) / 128; it++) {
            int i = tid + (it << 7);
            int c = i >> 5, j = i & 31;
            xs[c * (NK + 1) + j] = x[xbase + (size_t)c * HW_ + k0 + j];
        }
        // load S tile as m-pairs: ss2[m2][j] = (S[2m2][n], S[2m2+1][n])
        {
            int j = tid & 31;
            int m2b = tid >> 5;  // 0..3
#pragma unroll
            for (int it = 0; it < 8; it++) {
                int m2 = m2b + (it << 2);
                float s0 = S[sbase + (size_t)(2 * m2)     * HW_ + k0 + j];
                float s1 = S[sbase + (size_t)(2 * m2 + 1) * HW_ + k0 + j];
                ss2[m2 * (NK + 1) + j] = pk2(s0, s1);
            }
        }
        __syncthreads();

#pragma unroll
        for (int j = 0; j < NK; j++) {
            unsigned long long a2[8];
#pragma unroll
            for (int cc = 0; cc < 8; cc++) {
                float v = xs[(ty * 8 + cc) * (NK + 1) + j];
                a2[cc] = pk2(v, v);
            }
#pragma unroll
            for (int mp = 0; mp < 4; mp++) {
                unsigned long long b2 = ss2[(tx + 8 * mp) * (NK + 1) + j];
#pragma unroll
                for (int cc = 0; cc < 8; cc++) fma2(acc[cc][mp], a2[cc], b2);
            }
        }
    }

    float* Tb = T + ((size_t)b * C_ + c0) * M_;
#pragma unroll
    for (int cc = 0; cc < 8; cc++) {
#pragma unroll
        for (int mp = 0; mp < 4; mp++) {
            float2 u = unpk2(acc[cc][mp]);
            int m = 2 * (tx + 8 * mp);
            atomicAdd(&Tb[(size_t)(ty * 8 + cc) * M_ + m],     u.x);
            atomicAdd(&Tb[(size_t)(ty * 8 + cc) * M_ + m + 1], u.y);
        }
    }
}

// ---------------- launch ----------------
extern "C" void kernel_launch(void* const* d_in, const int* in_sizes, int n_in,
                              void* d_out, int out_size)
{
    const float* x  = (const float*)d_in[0];
    const float* Vw = (const float*)d_in[1];
    const float* Vb = (const float*)d_in[2];
    const float* U  = (const float*)d_in[3];

    float* out = (float*)d_out;
    float* T = out;                                  // [B, C, M]
    float* S = out + (size_t)B_ * C_ * M_;           // [B, M, N]

    const int tcount = B_ * C_ * M_;                 // 786432
    k_zero<<<(tcount + 255) / 256, 256>>>(T, tcount);
    k_proj_softmax<<<dim3(HW_ / 128, B_), 128>>>(x, Vw, Vb, U, S);
    k_pool<<<dim3(KSPLIT, C_ / CT, B_), 128>>>(x, S, T);
}

// round 2
// speedup vs baseline: 1.0158x; 1.0158x over previous
#include <cuda_runtime.h>

#define B_   32
#define C_   384
#define HW_  4096
#define M_   64
#define R_   16

#define CT     128            // c rows per pool block
#define NK     32             // K chunk
#define KSPLIT 8
#define KLEN   (HW_ / KSPLIT) // 512

typedef unsigned long long ull;

// ---------------- f32x2 helpers (packed fp32 FMA, sm_100+) ----------------
__device__ __forceinline__ ull pk2(float lo, float hi) {
    ull r;
    asm("mov.b64 %0, {%1, %2};" : "=l"(r) : "f"(lo), "f"(hi));
    return r;
}
__device__ __forceinline__ float2 unpk2(ull v) {
    float2 u;
    asm("mov.b64 {%0, %1}, %2;" : "=f"(u.x), "=f"(u.y) : "l"(v));
    return u;
}
__device__ __forceinline__ void fma2(ull &d, ull a, ull b) {
    asm("fma.rn.f32x2 %0, %1, %2, %0;" : "+l"(d) : "l"(a), "l"(b));
}

// ---------------- kernel 0: zero the T region of d_out ----------------
__global__ void k_zero(float* __restrict__ p, int n) {
    int i = blockIdx.x * blockDim.x + threadIdx.x;
    if (i < n) p[i] = 0.0f;
}

// ---------------- kernel 1: V = Vw x + Vb ; L = U V ; S = softmax_M(L) ----
// grid (HW_/128, B_), 128 threads; each thread owns one pixel n.
__global__ __launch_bounds__(128) void k_proj_softmax(
    const float* __restrict__ x,  const float* __restrict__ Vw,
    const float* __restrict__ Vb, const float* __restrict__ U,
    float* __restrict__ S)
{
    __shared__ __align__(16) ull sVw2[C_ * 8];   // [c][r2] pairs over r (24KB)
    __shared__ __align__(16) ull sUT2[R_ * 32];  // [r][m2] pairs over m (4KB)
    __shared__ float sVb[R_];

    const int tid = threadIdx.x;
    for (int i = tid; i < C_ * 8; i += 128) {
        int c = i >> 3, r2 = i & 7;
        sVw2[i] = pk2(Vw[(2 * r2) * C_ + c], Vw[(2 * r2 + 1) * C_ + c]);
    }
    for (int i = tid; i < R_ * 32; i += 128) {
        int r = i >> 5, m2 = i & 31;
        sUT2[i] = pk2(U[(2 * m2) * R_ + r], U[(2 * m2 + 1) * R_ + r]);
    }
    if (tid < R_) sVb[tid] = Vb[tid];
    __syncthreads();

    const int b = blockIdx.y;
    const int n = (blockIdx.x << 7) + tid;
    const float* xp = x + ((size_t)b * C_) * HW_ + n;

    ull V2[8];
#pragma unroll
    for (int r2 = 0; r2 < 8; r2++) V2[r2] = pk2(sVb[2 * r2], sVb[2 * r2 + 1]);

#pragma unroll 4
    for (int c = 0; c < C_; c++) {
        float xv = xp[(size_t)c * HW_];
        ull x2 = pk2(xv, xv);
        const ulonglong2* wr = (const ulonglong2*)&sVw2[c * 8];
        ulonglong2 w0 = wr[0], w1 = wr[1], w2 = wr[2], w3 = wr[3];
        fma2(V2[0], x2, w0.x); fma2(V2[1], x2, w0.y);
        fma2(V2[2], x2, w1.x); fma2(V2[3], x2, w1.y);
        fma2(V2[4], x2, w2.x); fma2(V2[5], x2, w2.y);
        fma2(V2[6], x2, w3.x); fma2(V2[7], x2, w3.y);
    }

    float V[R_];
#pragma unroll
    for (int r2 = 0; r2 < 8; r2++) {
        float2 u = unpk2(V2[r2]);
        V[2 * r2] = u.x; V[2 * r2 + 1] = u.y;
    }

    ull L2[32];
#pragma unroll
    for (int m2 = 0; m2 < 32; m2++) L2[m2] = 0ULL;
#pragma unroll
    for (int r = 0; r < R_; r++) {
        ull v2 = pk2(V[r], V[r]);
        const ulonglong2* ur = (const ulonglong2*)&sUT2[r * 32];
#pragma unroll
        for (int m4 = 0; m4 < 16; m4 += 2) {
            ulonglong2 ua = ur[m4 >> 1];
            fma2(L2[m4],     v2, ua.x);
            fma2(L2[m4 + 1], v2, ua.y);
        }
#pragma unroll
        for (int m4 = 16; m4 < 32; m4 += 2) {
            ulonglong2 ua = ur[m4 >> 1];
            fma2(L2[m4],     v2, ua.x);
            fma2(L2[m4 + 1], v2, ua.y);
        }
    }

    float L[M_];
#pragma unroll
    for (int m2 = 0; m2 < 32; m2++) {
        float2 u = unpk2(L2[m2]);
        L[2 * m2] = u.x; L[2 * m2 + 1] = u.y;
    }
    float mx = -1e30f;
#pragma unroll
    for (int m = 0; m < M_; m++) mx = fmaxf(mx, L[m]);
    float sum = 0.0f;
#pragma unroll
    for (int m = 0; m < M_; m++) { L[m] = __expf(L[m] - mx); sum += L[m]; }
    float inv = 1.0f / sum;

    float* sp = S + ((size_t)b * M_) * HW_ + n;
#pragma unroll
    for (int m = 0; m < M_; m++) sp[(size_t)m * HW_] = L[m] * inv;
}

// ---------------- kernel 2: T[b,c,m] += sum_n x[b,c,n] * S[b,m,n] ----------
// grid (KSPLIT, C_/CT, B_), 128 threads.
// Thread tile: 8 c-rows (ty+16k) x 8 m-cols (4 pairs, p = tx+8q).
// Inner loop: 12 LDS.64 + 32 fma2 per j — no packs, no index math.
__global__ __launch_bounds__(128) void k_pool(
    const float* __restrict__ x, const float* __restrict__ S,
    float* __restrict__ T)
{
    __shared__ ull xdup[CT * (NK + 1)];  // [c][j] as (x,x) pairs, row 33 (33.8KB)
    __shared__ ull sp2[NK * 33];         // [j][p] as (S[2p],S[2p+1]), row 33 (8.4KB)

    const int tid = threadIdx.x;
    const int tx = tid & 7;        // m-pair group
    const int ty = tid >> 3;       // c group (0..15)
    const int ks = blockIdx.x;
    const int c0 = blockIdx.y * CT;
    const int b  = blockIdx.z;

    const int jl = tid & 31;       // load-stage lane over j (coalesced)
    const int rl = tid >> 5;       // load-stage row group (0..3)

    const size_t xbase = ((size_t)b * C_ + c0) * HW_ + (size_t)ks * KLEN;
    const size_t sbase = ((size_t)b * M_) * HW_ + (size_t)ks * KLEN;

    ull acc[8][4];
#pragma unroll
    for (int k = 0; k < 8; k++)
#pragma unroll
        for (int q = 0; q < 4; q++) acc[k][q] = 0ULL;

    for (int k0 = 0; k0 < KLEN; k0 += NK) {
        __syncthreads();
        // x tile [CT x NK] -> duplicated pairs (coalesced gmem over j)
#pragma unroll
        for (int k = 0; k < 32; k++) {
            int c = rl + 4 * k;
            float v = x[xbase + (size_t)c * HW_ + k0 + jl];
            xdup[c * (NK + 1) + jl] = pk2(v, v);
        }
        // S tile: natural m-pairs (coalesced gmem over j)
#pragma unroll
        for (int q = 0; q < 8; q++) {
            int p = rl + 4 * q;
            float s0 = S[sbase + (size_t)(2 * p)     * HW_ + k0 + jl];
            float s1 = S[sbase + (size_t)(2 * p + 1) * HW_ + k0 + jl];
            sp2[jl * 33 + p] = pk2(s0, s1);
        }
        __syncthreads();

#pragma unroll
        for (int j = 0; j < NK; j++) {
            ull xv[8], sv[4];
#pragma unroll
            for (int k = 0; k < 8; k++)
                xv[k] = xdup[(ty + 16 * k) * (NK + 1) + j];
#pragma unroll
            for (int q = 0; q < 4; q++)
                sv[q] = sp2[j * 33 + tx + 8 * q];
#pragma unroll
            for (int k = 0; k < 8; k++)
#pragma unroll
                for (int q = 0; q < 4; q++)
                    fma2(acc[k][q], xv[k], sv[q]);
        }
    }

    float* Tb = T + ((size_t)b * C_ + c0) * M_;
#pragma unroll
    for (int k = 0; k < 8; k++) {
        int c = ty + 16 * k;
#pragma unroll
        for (int q = 0; q < 4; q++) {
            float2 u = unpk2(acc[k][q]);
            int m = 2 * (tx + 8 * q);
            atomicAdd(&Tb[(size_t)c * M_ + m],     u.x);
            atomicAdd(&Tb[(size_t)c * M_ + m + 1], u.y);
        }
    }
}

// ---------------- launch ----------------
extern "C" void kernel_launch(void* const* d_in, const int* in_sizes, int n_in,
                              void* d_out, int out_size)
{
    const float* x  = (const float*)d_in[0];
    const float* Vw = (const float*)d_in[1];
    const float* Vb = (const float*)d_in[2];
    const float* U  = (const float*)d_in[3];

    float* out = (float*)d_out;
    float* T = out;                           // [B, C, M]
    float* S = out + (size_t)B_ * C_ * M_;    // [B, M, N]

    const int tcount = B_ * C_ * M_;
    k_zero<<<(tcount + 255) / 256, 256>>>(T, tcount);
    k_proj_softmax<<<dim3(HW_ / 128, B_), 128>>>(x, Vw, Vb, U, S);
    k_pool<<<dim3(KSPLIT, C_ / CT, B_), 128>>>(x, S, T);
}

// round 5
// speedup vs baseline: 1.3360x; 1.3153x over previous
#include <cuda_runtime.h>
#include <cuda_bf16.h>
#include <cstdint>

#define B_   32
#define C_   384
#define HW_  4096
#define M_   64
#define R_   16

typedef unsigned long long ull;

// ---------------- f32x2 helpers (proj kernel) ----------------
__device__ __forceinline__ ull pk2(float lo, float hi) {
    ull r; asm("mov.b64 %0, {%1, %2};" : "=l"(r) : "f"(lo), "f"(hi)); return r;
}
__device__ __forceinline__ float2 unpk2(ull v) {
    float2 u; asm("mov.b64 {%0, %1}, %2;" : "=f"(u.x), "=f"(u.y) : "l"(v)); return u;
}
__device__ __forceinline__ void fma2(ull &d, ull a, ull b) {
    asm("fma.rn.f32x2 %0, %1, %2, %0;" : "+l"(d) : "l"(a), "l"(b));
}

// ---------------- kernel 1: V = Vw x + Vb ; L = U V ; S = softmax_M(L) ----
__global__ __launch_bounds__(128) void k_proj_softmax(
    const float* __restrict__ x,  const float* __restrict__ Vw,
    const float* __restrict__ Vb, const float* __restrict__ U,
    float* __restrict__ S)
{
    __shared__ __align__(16) ull sVw2[C_ * 8];
    __shared__ __align__(16) ull sUT2[R_ * 32];
    __shared__ float sVb[R_];

    const int tid = threadIdx.x;
    for (int i = tid; i < C_ * 8; i += 128) {
        int c = i >> 3, r2 = i & 7;
        sVw2[i] = pk2(Vw[(2 * r2) * C_ + c], Vw[(2 * r2 + 1) * C_ + c]);
    }
    for (int i = tid; i < R_ * 32; i += 128) {
        int r = i >> 5, m2 = i & 31;
        sUT2[i] = pk2(U[(2 * m2) * R_ + r], U[(2 * m2 + 1) * R_ + r]);
    }
    if (tid < R_) sVb[tid] = Vb[tid];
    __syncthreads();

    const int b = blockIdx.y;
    const int n = (blockIdx.x << 7) + tid;
    const float* xp = x + ((size_t)b * C_) * HW_ + n;

    ull V2[8];
#pragma unroll
    for (int r2 = 0; r2 < 8; r2++) V2[r2] = pk2(sVb[2 * r2], sVb[2 * r2 + 1]);

#pragma unroll 4
    for (int c = 0; c < C_; c++) {
        float xv = xp[(size_t)c * HW_];
        ull x2 = pk2(xv, xv);
        const ulonglong2* wr = (const ulonglong2*)&sVw2[c * 8];
        ulonglong2 w0 = wr[0], w1 = wr[1], w2 = wr[2], w3 = wr[3];
        fma2(V2[0], x2, w0.x); fma2(V2[1], x2, w0.y);
        fma2(V2[2], x2, w1.x); fma2(V2[3], x2, w1.y);
        fma2(V2[4], x2, w2.x); fma2(V2[5], x2, w2.y);
        fma2(V2[6], x2, w3.x); fma2(V2[7], x2, w3.y);
    }

    float V[R_];
#pragma unroll
    for (int r2 = 0; r2 < 8; r2++) {
        float2 u = unpk2(V2[r2]); V[2 * r2] = u.x; V[2 * r2 + 1] = u.y;
    }

    ull L2[32];
#pragma unroll
    for (int m2 = 0; m2 < 32; m2++) L2[m2] = 0ULL;
#pragma unroll
    for (int r = 0; r < R_; r++) {
        ull v2 = pk2(V[r], V[r]);
        const ulonglong2* ur = (const ulonglong2*)&sUT2[r * 32];
#pragma unroll
        for (int m4 = 0; m4 < 32; m4 += 2) {
            ulonglong2 ua = ur[m4 >> 1];
            fma2(L2[m4], v2, ua.x); fma2(L2[m4 + 1], v2, ua.y);
        }
    }

    float L[M_];
#pragma unroll
    for (int m2 = 0; m2 < 32; m2++) {
        float2 u = unpk2(L2[m2]); L[2 * m2] = u.x; L[2 * m2 + 1] = u.y;
    }
    float mx = -1e30f;
#pragma unroll
    for (int m = 0; m < M_; m++) mx = fmaxf(mx, L[m]);
    float sum = 0.0f;
#pragma unroll
    for (int m = 0; m < M_; m++) { L[m] = __expf(L[m] - mx); sum += L[m]; }
    float inv = 1.0f / sum;

    float* sp = S + ((size_t)b * M_) * HW_ + n;
#pragma unroll
    for (int m = 0; m < M_; m++) sp[(size_t)m * HW_] = L[m] * inv;
}

// ================= pool kernel: warp-level bf16 mma.sync =================
// Per block (c-tile 128, batch b): T[c0+0:128, 0:64] = sum_n x[c,n] S[m,n]
// fp32 split into bf16 (hi, lo); 3-term compensated MMA: AhBh + AhBl + AlBh.

#define CTILE  128
#define KC     64
#define NCHUNK (HW_ / KC)   // 64

// dynamic smem layout (bytes): bf16 tiles, rows of 64 bf16 = 128B, SW128 swizzle
#define SM_AHI 0
#define SM_ALO 16384
#define SM_BHI 32768
#define SM_BLO 40960
#define SM_TOTAL 49152

__device__ __forceinline__ uint32_t smem_u32(const void* p) {
    uint32_t a;
    asm("{ .reg .u64 t; cvta.to.shared.u64 t, %1; cvt.u32.u64 %0, t; }"
        : "=r"(a) : "l"(p));
    return a;
}
__device__ __forceinline__ uint32_t sw128(uint32_t off) {
    return off ^ ((off >> 3) & 0x70);
}
__device__ __forceinline__ void ldsm4(uint32_t* r, uint32_t addr) {
    asm volatile("ldmatrix.sync.aligned.m8n8.x4.shared.b16 {%0,%1,%2,%3}, [%4];"
        : "=r"(r[0]), "=r"(r[1]), "=r"(r[2]), "=r"(r[3]) : "r"(addr));
}
__device__ __forceinline__ void mma_bf16(float* d, const uint32_t* a,
                                         const uint32_t* b) {
    asm volatile(
        "mma.sync.aligned.m16n8k16.row.col.f32.bf16.bf16.f32 "
        "{%0,%1,%2,%3}, {%4,%5,%6,%7}, {%8,%9}, {%0,%1,%2,%3};"
        : "+f"(d[0]), "+f"(d[1]), "+f"(d[2]), "+f"(d[3])
        : "r"(a[0]), "r"(a[1]), "r"(a[2]), "r"(a[3]), "r"(b[0]), "r"(b[1]));
}

__global__ __launch_bounds__(256, 1) void k_pool_mma(
    const float* __restrict__ x, const float* __restrict__ S,
    float* __restrict__ T)
{
    extern __shared__ char smem[];
    const uint32_t sb = smem_u32(smem);
    const int tid = threadIdx.x;
    const int w   = tid >> 5;
    const int l   = tid & 31;
    const int c0  = blockIdx.x * CTILE;
    const int b   = blockIdx.y;

    const float* xb = x + ((size_t)b * C_ + c0) * HW_;
    const float* Sb = S + (size_t)b * M_ * HW_;

    // staging lanes: cp = column pair (bytes 4*cp in 128B row), r0 = row group
    const int cp = tid & 31;
    const int r0 = tid >> 5;

    // ldmatrix lane addressing (constant per thread)
    const int arow = 16 * w + (l & 15);
    const int acol = (l >> 4) * 16;                    // bytes
    const int nrow = (l & 7) + ((l >> 4) << 3);
    const int bcol = ((l >> 3) & 1) * 16;              // bytes

    float acc[8][4];
#pragma unroll
    for (int j = 0; j < 8; j++)
#pragma unroll
        for (int q = 0; q < 4; q++) acc[j][q] = 0.0f;

    // prefetch chunk 0
    float2 av[16], bv[8];
#pragma unroll
    for (int i = 0; i < 16; i++)
        av[i] = *(const float2*)(xb + (size_t)(r0 + 8 * i) * HW_ + 2 * cp);
#pragma unroll
    for (int i = 0; i < 8; i++)
        bv[i] = *(const float2*)(Sb + (size_t)(r0 + 8 * i) * HW_ + 2 * cp);

    for (int ch = 0; ch < NCHUNK; ch++) {
        // convert fp32 -> bf16 hi/lo into swizzled smem
#pragma unroll
        for (int i = 0; i < 16; i++) {
            uint32_t sw = sw128((r0 + 8 * i) * 128 + 4 * cp);
            __nv_bfloat162 h = __floats2bfloat162_rn(av[i].x, av[i].y);
            float rx = av[i].x - __bfloat162float(h.x);
            float ry = av[i].y - __bfloat162float(h.y);
            __nv_bfloat162 lo = __floats2bfloat162_rn(rx, ry);
            *(uint32_t*)(smem + SM_AHI + sw) = *(uint32_t*)&h;
            *(uint32_t*)(smem + SM_ALO + sw) = *(uint32_t*)&lo;
        }
#pragma unroll
        for (int i = 0; i < 8; i++) {
            uint32_t sw = sw128((r0 + 8 * i) * 128 + 4 * cp);
            __nv_bfloat162 h = __floats2bfloat162_rn(bv[i].x, bv[i].y);
            float rx = bv[i].x - __bfloat162float(h.x);
            float ry = bv[i].y - __bfloat162float(h.y);
            __nv_bfloat162 lo = __floats2bfloat162_rn(rx, ry);
            *(uint32_t*)(smem + SM_BHI + sw) = *(uint32_t*)&h;
            *(uint32_t*)(smem + SM_BLO + sw) = *(uint32_t*)&lo;
        }
        __syncthreads();

        // prefetch next chunk while computing this one
        if (ch + 1 < NCHUNK) {
            const int k1 = (ch + 1) * KC;
#pragma unroll
            for (int i = 0; i < 16; i++)
                av[i] = *(const float2*)(xb + (size_t)(r0 + 8 * i) * HW_ + k1 + 2 * cp);
#pragma unroll
            for (int i = 0; i < 8; i++)
                bv[i] = *(const float2*)(Sb + (size_t)(r0 + 8 * i) * HW_ + k1 + 2 * cp);
        }

        // compute: 4 k-steps of 16
#pragma unroll
        for (int s = 0; s < 4; s++) {
            uint32_t ah[4], al[4];
            uint32_t asw = sw128(arow * 128 + 32 * s + acol);
            ldsm4(ah, sb + SM_AHI + asw);
            ldsm4(al, sb + SM_ALO + asw);
#pragma unroll
            for (int jp = 0; jp < 4; jp++) {
                uint32_t bh[4], bl[4];
                uint32_t bsw = sw128((16 * jp + nrow) * 128 + 32 * s + bcol);
                ldsm4(bh, sb + SM_BHI + bsw);
                ldsm4(bl, sb + SM_BLO + bsw);
                mma_bf16(acc[2 * jp],     ah, bh);
                mma_bf16(acc[2 * jp],     ah, bl);
                mma_bf16(acc[2 * jp],     al, bh);
                mma_bf16(acc[2 * jp + 1], ah, bh + 2);
                mma_bf16(acc[2 * jp + 1], ah, bl + 2);
                mma_bf16(acc[2 * jp + 1], al, bh + 2);
            }
        }
        __syncthreads();
    }

    // store: warp w owns rows 16w..16w+15; thread: rows g, g+8; cols 8j+2(l&3)
    const int g  = l >> 2;
    const int q2 = (l & 3) * 2;
    float* tb = T + ((size_t)b * C_ + c0 + 16 * w) * M_;
#pragma unroll
    for (int j = 0; j < 8; j++) {
        float2 v0 = make_float2(acc[j][0], acc[j][1]);
        float2 v1 = make_float2(acc[j][2], acc[j][3]);
        *(float2*)(tb + (size_t)g * M_ + 8 * j + q2)       = v0;
        *(float2*)(tb + (size_t)(g + 8) * M_ + 8 * j + q2) = v1;
    }
}

// ---------------- launch ----------------
extern "C" void kernel_launch(void* const* d_in, const int* in_sizes, int n_in,
                              void* d_out, int out_size)
{
    const float* x  = (const float*)d_in[0];
    const float* Vw = (const float*)d_in[1];
    const float* Vb = (const float*)d_in[2];
    const float* U  = (const float*)d_in[3];

    float* out = (float*)d_out;
    float* T = out;                           // [B, C, M]
    float* S = out + (size_t)B_ * C_ * M_;    // [B, M, N]

    cudaFuncSetAttribute(k_pool_mma, cudaFuncAttributeMaxDynamicSharedMemorySize,
                         SM_TOTAL);
    k_proj_softmax<<<dim3(HW_ / 128, B_), 128>>>(x, Vw, Vb, U, S);
    k_pool_mma<<<dim3(C_ / CTILE, B_), 256, SM_TOTAL>>>(x, S, T);
}